// round 1
// baseline (speedup 1.0000x reference)
#include <cuda_runtime.h>

#define Bn 8
#define Dn 192
#define Hn 64
#define Wn 64
#define Ln 4096
#define Nn 16
#define Rn 6
#define Cn 38
#define Kn 4

// scratch (allocation-free: device globals)
__device__ float g_DU[(size_t)Bn*Kn*Ln*Dn*2];   // (b,k,l,d,{delta,u})  201MB
__device__ float g_BC[(size_t)Bn*Kn*Ln*Nn*2];   // (b,k,l,n,{B,C})      16.8MB
__device__ float g_ys[(size_t)Bn*Kn*Dn*Ln];     // (b,k,d,l)            100MB

__device__ __forceinline__ float ex2f(float x){
    float r; asm("ex2.approx.ftz.f32 %0, %1;" : "=f"(r) : "f"(x)); return r;
}

// ---------------------------------------------------------------------------
// Kernel A: cross-scan gather + x_proj + dt_proj + softplus.
// Block = (b, k, tile of 32 sequence positions). For k=1,3 the 32 positions are
// chosen stride-64 in l so the x gather (pos) is contiguous -> coalesced.
// ---------------------------------------------------------------------------
__global__ __launch_bounds__(256) void proj_kernel(
    const float* __restrict__ x, const float* __restrict__ xpw,
    const float* __restrict__ dtw, const float* __restrict__ dtb)
{
    __shared__ float xt[Dn*32];        // xt[d][j]
    __shared__ float dts_s[Rn][32];

    const int bid = blockIdx.x;
    const int t   = bid & 127;
    const int k   = (bid >> 7) & 3;
    const int b   = bid >> 9;
    const int tid = threadIdx.x;

    int l0, lstep, p0, pstep;
    if (k == 0)      { l0 = t*32; lstep = 1;  p0 = t*32;        pstep = 1;  }
    else if (k == 2) { l0 = t*32; lstep = 1;  p0 = 4095 - t*32; pstep = -1; }
    else {
        int h = t & 63, w0 = (t >> 6) * 32;
        p0 = h*64 + w0; pstep = 1;
        if (k == 1) { l0 = w0*64 + h;          lstep = 64;  }
        else        { l0 = 4095 - (w0*64 + h); lstep = -64; }
    }

    const float* xb = x + (size_t)b*Dn*Ln;
    for (int idx = tid; idx < Dn*32; idx += 256) {
        int d = idx >> 5, j = idx & 31;
        xt[idx] = xb[(size_t)d*Ln + p0 + j*pstep];
    }
    __syncthreads();

    {   // x_dbl = W_proj[k] @ xvec ; split into dts / B / C
        const int j  = tid & 31;
        const int cg = tid >> 5;
        const int l  = l0 + j*lstep;
        const size_t bkl = (size_t)(b*Kn + k)*Ln + l;
        for (int c = cg; c < Cn; c += 8) {
            const float4* wr = (const float4*)(xpw + (size_t)(k*Cn + c)*Dn);
            float acc = 0.f;
            #pragma unroll
            for (int i = 0; i < Dn/4; i++) {
                float4 wv = wr[i];
                acc += wv.x * xt[(4*i+0)*32 + j];
                acc += wv.y * xt[(4*i+1)*32 + j];
                acc += wv.z * xt[(4*i+2)*32 + j];
                acc += wv.w * xt[(4*i+3)*32 + j];
            }
            if (c < Rn) dts_s[c][j] = acc;
            else {
                int n = c - Rn, half = 0;
                if (n >= Nn) { n -= Nn; half = 1; }
                g_BC[(bkl*Nn + n)*2 + half] = acc;   // interleave B,C
            }
        }
    }
    __syncthreads();

    // delta = softplus(dt_w @ dts + bias); store (delta, u) interleaved
    for (int idx = tid; idx < Dn*32; idx += 256) {
        int d = idx % Dn, j = idx / Dn;
        float acc = dtb[k*Dn + d];
        #pragma unroll
        for (int r = 0; r < Rn; r++) acc += dts_s[r][j] * dtw[(k*Dn + d)*Rn + r];
        float delta = (acc > 20.f) ? acc : log1pf(expf(acc));
        float u = xt[d*32 + j];
        int l = l0 + j*lstep;
        size_t o = ((size_t)(b*Kn + k)*Ln + l)*Dn + d;
        ((float2*)g_DU)[o] = make_float2(delta, u);
    }
}

// ---------------------------------------------------------------------------
// Kernel B: selective scan. 1 warp = 4 channels; lane = (dd<<3)|nn owns states
// {2nn, 2nn+1} of channel d = grp*4+dd. Per step: 1 LDG.64 + 1 LDG.128,
// 2 EX2, recurrence FMAs, 3-shfl reduce. y buffered 4 steps -> STG.128.
// ---------------------------------------------------------------------------
__global__ __launch_bounds__(128) void scan_kernel(
    const float* __restrict__ A_logs, const float* __restrict__ Ds)
{
    const int g    = blockIdx.x*4 + (threadIdx.x >> 5);   // 0..1535
    const int lane = threadIdx.x & 31;
    const int bk   = g / 48;
    const int grp  = g - bk*48;
    const int dd   = lane >> 3, nn = lane & 7;
    const int d    = grp*4 + dd;
    const int k    = bk & 3;
    const int kd   = k*Dn + d;
    const float LOG2E = 1.4426950408889634f;
    const float A0 = -expf(A_logs[kd*Nn + 2*nn])   * LOG2E;
    const float A1 = -expf(A_logs[kd*Nn + 2*nn+1]) * LOG2E;
    const float Dd = Ds[kd];

    const float2* __restrict__ du_p = ((const float2*)g_DU) + (size_t)bk*Ln*Dn + d;
    const float4* __restrict__ bc_p = ((const float4*)g_BC) + (size_t)bk*Ln*8 + nn;
    float* __restrict__ ysb = g_ys + ((size_t)bk*Dn + d)*Ln;

    float h0 = 0.f, h1 = 0.f;
    for (int l = 0; l < Ln; l += 4) {
        float yb[4];
        #pragma unroll
        for (int q = 0; q < 4; q++) {
            float2 du = du_p[(size_t)(l+q)*Dn];
            float4 bc = bc_p[(size_t)(l+q)*8];
            float dt = du.x, u = du.y;
            float dA0 = ex2f(dt * A0);
            float dA1 = ex2f(dt * A1);
            float dtu = dt * u;
            h0 = fmaf(dA0, h0, dtu*bc.x);
            h1 = fmaf(dA1, h1, dtu*bc.z);
            float p = fmaf(h1, bc.w, h0*bc.y);
            p += __shfl_xor_sync(0xffffffffu, p, 4);
            p += __shfl_xor_sync(0xffffffffu, p, 2);
            p += __shfl_xor_sync(0xffffffffu, p, 1);
            yb[q] = fmaf(Dd, u, p);
        }
        if (nn == 0) *(float4*)(ysb + l) = make_float4(yb[0], yb[1], yb[2], yb[3]);
    }
}

// ---------------------------------------------------------------------------
// Kernel C: CrossMerge + LayerNorm. 8w x 4h spatial tile staged in smem so all
// four direction reads are (at least half-)sector aligned.
// ---------------------------------------------------------------------------
__global__ __launch_bounds__(256) void merge_ln_kernel(
    const float* __restrict__ gamma, const float* __restrict__ beta,
    float* __restrict__ out)
{
    __shared__ float ysm[32*193];     // [pos=hh*8+ww][d], padded
    const int bx = blockIdx.x;        // b*(16*8) + hb*8 + wb
    const int b  = bx >> 7;
    const int h0 = ((bx >> 3) & 15) * 4;
    const int w0 = (bx & 7) * 8;
    const int tid = threadIdx.x;

    const float* ys0 = g_ys + (size_t)(b*4+0)*Dn*Ln;
    const float* ys1 = g_ys + (size_t)(b*4+1)*Dn*Ln;
    const float* ys2 = g_ys + (size_t)(b*4+2)*Dn*Ln;
    const float* ys3 = g_ys + (size_t)(b*4+3)*Dn*Ln;

    // k=0: row-major direct
    for (int idx = tid; idx < Dn*32; idx += 256) {
        int ww = idx & 7, hh = (idx >> 3) & 3, d = idx >> 5;
        int l = (h0+hh)*64 + w0 + ww;
        ysm[(hh*8+ww)*193 + d] = ys0[(size_t)d*Ln + l];
    }
    __syncthreads();
    // k=2: row-major reversed
    for (int idx = tid; idx < Dn*32; idx += 256) {
        int ww = idx & 7, hh = (idx >> 3) & 3, d = idx >> 5;
        int l = (h0+hh)*64 + w0 + ww;
        ysm[(hh*8+ww)*193 + d] += ys2[(size_t)d*Ln + (4095 - l)];
    }
    __syncthreads();
    // k=1: transposed (lT = w*64 + h), lanes fast over h for coalescing
    for (int idx = tid; idx < Dn*32; idx += 256) {
        int hh = idx & 3, ww = (idx >> 2) & 7, d = idx >> 5;
        int lT = (w0+ww)*64 + h0 + hh;
        ysm[(hh*8+ww)*193 + d] += ys1[(size_t)d*Ln + lT];
    }
    __syncthreads();
    // k=3: transposed reversed
    for (int idx = tid; idx < Dn*32; idx += 256) {
        int hh = idx & 3, ww = (idx >> 2) & 7, d = idx >> 5;
        int lT = (w0+ww)*64 + h0 + hh;
        ysm[(hh*8+ww)*193 + d] += ys3[(size_t)d*Ln + (4095 - lT)];
    }
    __syncthreads();

    // LayerNorm over D=192: warp per position, 6 d's per lane
    const int warp = tid >> 5, lane = tid & 31;
    float gam[6], bet[6];
    #pragma unroll
    for (int i = 0; i < 6; i++) { gam[i] = gamma[lane+32*i]; bet[i] = beta[lane+32*i]; }
    for (int pp = warp; pp < 32; pp += 8) {
        float yv[6]; float s = 0.f;
        #pragma unroll
        for (int i = 0; i < 6; i++) { yv[i] = ysm[pp*193 + lane + 32*i]; s += yv[i]; }
        #pragma unroll
        for (int o = 16; o; o >>= 1) s += __shfl_xor_sync(0xffffffffu, s, o);
        float mean = s * (1.f/192.f);
        float v = 0.f;
        #pragma unroll
        for (int i = 0; i < 6; i++) { float z = yv[i]-mean; v += z*z; }
        #pragma unroll
        for (int o = 16; o; o >>= 1) v += __shfl_xor_sync(0xffffffffu, v, o);
        float rstd = rsqrtf(v*(1.f/192.f) + 1e-5f);
        int hh = pp >> 3, ww = pp & 7;
        int l = (h0+hh)*64 + w0 + ww;
        size_t ob = ((size_t)b*Ln + l)*Dn;
        #pragma unroll
        for (int i = 0; i < 6; i++)
            out[ob + lane + 32*i] = fmaf((yv[i]-mean)*rstd, gam[i], bet[i]);
    }
}

extern "C" void kernel_launch(void* const* d_in, const int* in_sizes, int n_in,
                              void* d_out, int out_size) {
    const float* x    = (const float*)d_in[0];
    const float* xpw  = (const float*)d_in[1];
    const float* dtw  = (const float*)d_in[2];
    const float* dtb  = (const float*)d_in[3];
    const float* Alog = (const float*)d_in[4];
    const float* Ds   = (const float*)d_in[5];
    const float* gam  = (const float*)d_in[6];
    const float* bet  = (const float*)d_in[7];
    float* out = (float*)d_out;

    proj_kernel<<<Bn*Kn*128, 256>>>(x, xpw, dtw, dtb);   // 4096 blocks
    scan_kernel<<<384, 128>>>(Alog, Ds);                 // 1536 warps
    merge_ln_kernel<<<1024, 256>>>(gam, bet, out);       // 8 * 16 * 8 tiles
}

// round 2
// speedup vs baseline: 3.0635x; 3.0635x over previous
#include <cuda_runtime.h>

#define Bn 8
#define Dn 192
#define Ln 4096
#define Nn 16
#define Rn 6
#define Cn 38
#define Kn 4
#define NC 32
#define Lc 128

// scratch (allocation-free device globals)
__device__ float g_DU[(size_t)Bn*Kn*Ln*Dn*2];        // (bk,l,d,{dt,u})
__device__ float g_BC[(size_t)Bn*Kn*Ln*Nn*2];        // (bk,l,n,{B,C})
__device__ float g_ys[(size_t)Bn*Kn*Ln*Dn];          // (bk,l,d)
__device__ float g_hend[(size_t)Bn*Kn*NC*Dn*Nn];     // (bk,c,d,n)  p1 out -> overwritten w/ hinit
__device__ float g_S[(size_t)Bn*Kn*NC*Dn];           // (bk,c,d)

__device__ __forceinline__ float ex2f(float x){
    float r; asm("ex2.approx.ftz.f32 %0, %1;" : "=f"(r) : "f"(x)); return r;
}
__device__ __forceinline__ float lg2f(float x){
    float r; asm("lg2.approx.ftz.f32 %0, %1;" : "=f"(r) : "f"(x)); return r;
}

// ---------------------------------------------------------------------------
// Kernel A: cross-scan gather + x_proj + dt_proj + softplus.
// Block = (b,k, 32 seq positions). Thread accumulates 5 output channels to
// amortize LDS reads of the x vector.
// ---------------------------------------------------------------------------
__global__ __launch_bounds__(256) void proj_kernel(
    const float* __restrict__ x, const float* __restrict__ xpw,
    const float* __restrict__ dtw, const float* __restrict__ dtb)
{
    __shared__ float xt[Dn*32];        // xt[d][j]
    __shared__ float dts_s[Rn][32];

    const int bid = blockIdx.x;
    const int t   = bid & 127;
    const int k   = (bid >> 7) & 3;
    const int b   = bid >> 9;
    const int tid = threadIdx.x;

    int l0, lstep, p0, pstep;
    if (k == 0)      { l0 = t*32; lstep = 1;  p0 = t*32;        pstep = 1;  }
    else if (k == 2) { l0 = t*32; lstep = 1;  p0 = 4095 - t*32; pstep = -1; }
    else {
        int h = t & 63, w0 = (t >> 6) * 32;
        p0 = h*64 + w0; pstep = 1;
        if (k == 1) { l0 = w0*64 + h;          lstep = 64;  }
        else        { l0 = 4095 - (w0*64 + h); lstep = -64; }
    }

    const float* xb = x + (size_t)b*Dn*Ln;
    for (int idx = tid; idx < Dn*32; idx += 256) {
        int d = idx >> 5, j = idx & 31;
        xt[idx] = xb[(size_t)d*Ln + p0 + j*pstep];
    }
    __syncthreads();

    {
        const int j = tid & 31;
        const int w = tid >> 5;
        const int l = l0 + j*lstep;
        const size_t bkl = (size_t)(b*Kn + k)*Ln + l;

        float acc[5] = {0.f,0.f,0.f,0.f,0.f};
        const float4* wp[5];
        #pragma unroll
        for (int m = 0; m < 5; m++) {
            int c = w + 8*m; if (c > Cn-1) c = Cn-1;
            wp[m] = (const float4*)(xpw + (size_t)(k*Cn + c)*Dn);
        }
        #pragma unroll 4
        for (int i = 0; i < Dn/4; i++) {
            float x0 = xt[(4*i+0)*32 + j];
            float x1 = xt[(4*i+1)*32 + j];
            float x2 = xt[(4*i+2)*32 + j];
            float x3 = xt[(4*i+3)*32 + j];
            #pragma unroll
            for (int m = 0; m < 5; m++) {
                float4 wv = wp[m][i];
                acc[m] = fmaf(wv.x, x0, acc[m]);
                acc[m] = fmaf(wv.y, x1, acc[m]);
                acc[m] = fmaf(wv.z, x2, acc[m]);
                acc[m] = fmaf(wv.w, x3, acc[m]);
            }
        }
        #pragma unroll
        for (int m = 0; m < 5; m++) {
            int c = w + 8*m;
            if (c < Rn) dts_s[c][j] = acc[m];
            else if (c < Cn) {
                int n = c - Rn, half = 0;
                if (n >= Nn) { n -= Nn; half = 1; }
                g_BC[(bkl*Nn + n)*2 + half] = acc[m];
            }
        }
    }
    __syncthreads();

    // delta = softplus(dt_w @ dts + bias); store (delta,u) interleaved
    for (int idx = tid; idx < Dn*32; idx += 256) {
        int d = idx % Dn, j = idx / Dn;
        float acc = dtb[k*Dn + d];
        #pragma unroll
        for (int r = 0; r < Rn; r++) acc = fmaf(dts_s[r][j], dtw[(k*Dn + d)*Rn + r], acc);
        float e = ex2f(acc * 1.4426950408889634f);
        float sp = 0.6931471805599453f * lg2f(1.f + e);
        if (acc > 20.f) sp = acc;
        float u = xt[d*32 + j];
        int l = l0 + j*lstep;
        size_t o = ((size_t)(b*Kn + k)*Ln + l)*Dn + d;
        ((float2*)g_DU)[o] = make_float2(sp, u);
    }
}

// ---------------------------------------------------------------------------
// Scan pass 1: per-chunk local scan from h=0. Lane owns one channel d,
// h[16] in registers. Emits h_end and sum(dt).
// ---------------------------------------------------------------------------
__global__ __launch_bounds__(192) void scan_p1(const float* __restrict__ A_logs)
{
    __shared__ float4 sBC[Lc*8];
    const int bk = blockIdx.x >> 5;
    const int c  = blockIdx.x & 31;
    const int d  = threadIdx.x;
    const int k  = bk & 3;

    const float4* gbc = (const float4*)(g_BC + ((size_t)bk*Ln + (size_t)c*Lc)*32);
    for (int i = d; i < Lc*8; i += 192) sBC[i] = gbc[i];
    __syncthreads();

    float A[16];
    const float4* al = (const float4*)(A_logs + (size_t)(k*Dn + d)*16);
    #pragma unroll
    for (int m = 0; m < 4; m++) {
        float4 v = al[m];
        A[4*m+0] = -expf(v.x) * 1.4426950408889634f;
        A[4*m+1] = -expf(v.y) * 1.4426950408889634f;
        A[4*m+2] = -expf(v.z) * 1.4426950408889634f;
        A[4*m+3] = -expf(v.w) * 1.4426950408889634f;
    }

    float h[16];
    #pragma unroll
    for (int n = 0; n < 16; n++) h[n] = 0.f;
    float S = 0.f;
    const float2* du = ((const float2*)g_DU) + ((size_t)bk*Ln + (size_t)c*Lc)*Dn + d;

    for (int t = 0; t < Lc; t++) {
        float2 duv = du[(size_t)t*Dn];
        float dt = duv.x, dtu = dt*duv.y;
        S += dt;
        #pragma unroll
        for (int m = 0; m < 8; m++) {
            float4 q = sBC[t*8 + m];
            h[2*m]   = fmaf(ex2f(dt*A[2*m]),   h[2*m],   dtu*q.x);
            h[2*m+1] = fmaf(ex2f(dt*A[2*m+1]), h[2*m+1], dtu*q.z);
        }
    }
    float4* out = (float4*)(g_hend + (((size_t)bk*NC + c)*Dn + d)*16);
    #pragma unroll
    for (int m = 0; m < 4; m++) out[m] = make_float4(h[4*m], h[4*m+1], h[4*m+2], h[4*m+3]);
    g_S[((size_t)bk*NC + c)*Dn + d] = S;
}

// ---------------------------------------------------------------------------
// Scan mid: chain chunk summaries -> exclusive h_init prefix (in place).
// Thread owns one (bk,d,n).
// ---------------------------------------------------------------------------
__global__ __launch_bounds__(256) void scan_mid(const float* __restrict__ A_logs)
{
    int gid = blockIdx.x*256 + threadIdx.x;
    if (gid >= 32*Dn*Nn) return;
    int n  = gid & 15;
    int d  = (gid >> 4) % Dn;
    int bk = gid / (Dn*16);
    int k  = bk & 3;
    float A = -expf(A_logs[(size_t)(k*Dn + d)*16 + n]) * 1.4426950408889634f;
    float h = 0.f;
    for (int c = 0; c < NC; c++) {
        size_t o = (((size_t)bk*NC + c)*Dn + d)*16 + n;
        float hend = g_hend[o];
        float S = g_S[((size_t)bk*NC + c)*Dn + d];
        g_hend[o] = h;                       // exclusive prefix
        h = fmaf(ex2f(A*S), h, hend);
    }
}

// ---------------------------------------------------------------------------
// Scan pass 2: rescan chunk from h_init, emit y in (bk,l,d) layout (coalesced).
// ---------------------------------------------------------------------------
__global__ __launch_bounds__(192) void scan_p2(
    const float* __restrict__ A_logs, const float* __restrict__ Ds)
{
    __shared__ float4 sBC[Lc*8];
    const int bk = blockIdx.x >> 5;
    const int c  = blockIdx.x & 31;
    const int d  = threadIdx.x;
    const int k  = bk & 3;

    const float4* gbc = (const float4*)(g_BC + ((size_t)bk*Ln + (size_t)c*Lc)*32);
    for (int i = d; i < Lc*8; i += 192) sBC[i] = gbc[i];
    __syncthreads();

    float A[16];
    const float4* al = (const float4*)(A_logs + (size_t)(k*Dn + d)*16);
    #pragma unroll
    for (int m = 0; m < 4; m++) {
        float4 v = al[m];
        A[4*m+0] = -expf(v.x) * 1.4426950408889634f;
        A[4*m+1] = -expf(v.y) * 1.4426950408889634f;
        A[4*m+2] = -expf(v.z) * 1.4426950408889634f;
        A[4*m+3] = -expf(v.w) * 1.4426950408889634f;
    }

    float h[16];
    const float4* hin = (const float4*)(g_hend + (((size_t)bk*NC + c)*Dn + d)*16);
    #pragma unroll
    for (int m = 0; m < 4; m++) {
        float4 v = hin[m];
        h[4*m+0] = v.x; h[4*m+1] = v.y; h[4*m+2] = v.z; h[4*m+3] = v.w;
    }
    const float Dd = Ds[k*Dn + d];

    const float2* du = ((const float2*)g_DU) + ((size_t)bk*Ln + (size_t)c*Lc)*Dn + d;
    float* yo = g_ys + ((size_t)bk*Ln + (size_t)c*Lc)*Dn + d;

    for (int t = 0; t < Lc; t++) {
        float2 duv = du[(size_t)t*Dn];
        float dt = duv.x, u = duv.y, dtu = dt*u;
        float pa = 0.f, pb = 0.f;
        #pragma unroll
        for (int m = 0; m < 8; m++) {
            float4 q = sBC[t*8 + m];
            h[2*m]   = fmaf(ex2f(dt*A[2*m]),   h[2*m],   dtu*q.x);
            h[2*m+1] = fmaf(ex2f(dt*A[2*m+1]), h[2*m+1], dtu*q.z);
            pa = fmaf(h[2*m],   q.y, pa);
            pb = fmaf(h[2*m+1], q.w, pb);
        }
        yo[(size_t)t*Dn] = fmaf(Dd, u, pa + pb);
    }
}

// ---------------------------------------------------------------------------
// CrossMerge + LayerNorm. y layout is (bk,l,d): every gather is a contiguous
// 768B channel vector. Warp per output position; no smem.
// ---------------------------------------------------------------------------
__global__ __launch_bounds__(256) void merge_ln_kernel(
    const float* __restrict__ gamma, const float* __restrict__ beta,
    float* __restrict__ out)
{
    const int bid  = blockIdx.x;          // 8 * 512
    const int b    = bid >> 9;
    const int l    = ((bid & 511) << 3) + (threadIdx.x >> 5);
    const int lane = threadIdx.x & 31;
    const int hh = l >> 6, ww = l & 63;
    const int lT = ww*64 + hh;

    const float* y0 = g_ys + ((size_t)(b*4+0)*Ln + l)*Dn;
    const float* y1 = g_ys + ((size_t)(b*4+1)*Ln + lT)*Dn;
    const float* y2 = g_ys + ((size_t)(b*4+2)*Ln + (4095 - l))*Dn;
    const float* y3 = g_ys + ((size_t)(b*4+3)*Ln + (4095 - lT))*Dn;

    float v[6]; float s = 0.f;
    #pragma unroll
    for (int i = 0; i < 6; i++) {
        int dd = lane + 32*i;
        v[i] = y0[dd] + y1[dd] + y2[dd] + y3[dd];
        s += v[i];
    }
    #pragma unroll
    for (int o = 16; o; o >>= 1) s += __shfl_xor_sync(0xffffffffu, s, o);
    float mean = s * (1.f/192.f);
    float var = 0.f;
    #pragma unroll
    for (int i = 0; i < 6; i++) { float z = v[i] - mean; var = fmaf(z, z, var); }
    #pragma unroll
    for (int o = 16; o; o >>= 1) var += __shfl_xor_sync(0xffffffffu, var, o);
    float rstd = rsqrtf(var*(1.f/192.f) + 1e-5f);

    size_t ob = ((size_t)b*Ln + l)*Dn;
    #pragma unroll
    for (int i = 0; i < 6; i++) {
        int dd = lane + 32*i;
        out[ob + dd] = fmaf((v[i] - mean)*rstd, gamma[dd], beta[dd]);
    }
}

extern "C" void kernel_launch(void* const* d_in, const int* in_sizes, int n_in,
                              void* d_out, int out_size) {
    const float* x    = (const float*)d_in[0];
    const float* xpw  = (const float*)d_in[1];
    const float* dtw  = (const float*)d_in[2];
    const float* dtb  = (const float*)d_in[3];
    const float* Alog = (const float*)d_in[4];
    const float* Ds   = (const float*)d_in[5];
    const float* gam  = (const float*)d_in[6];
    const float* bet  = (const float*)d_in[7];
    float* out = (float*)d_out;

    proj_kernel<<<Bn*Kn*128, 256>>>(x, xpw, dtw, dtb);
    scan_p1<<<32*NC, 192>>>(Alog);
    scan_mid<<<(32*Dn*Nn + 255)/256, 256>>>(Alog);
    scan_p2<<<32*NC, 192>>>(Alog, Ds);
    merge_ln_kernel<<<Bn*512, 256>>>(gam, bet, out);
}

// round 3
// speedup vs baseline: 3.0831x; 1.0064x over previous
#include <cuda_runtime.h>

#define Bn 8
#define Dn 192
#define Ln 4096
#define Nn 16
#define Rn 6
#define Cn 38
#define Kn 4
#define NC 32
#define Lc 128

// scratch (allocation-free device globals)
__device__ float g_DU[(size_t)Bn*Kn*Ln*Dn*2];        // (bk,l,d,{dt,u})
__device__ float g_BC[(size_t)Bn*Kn*Ln*Nn*2];        // (bk,l,n,{B,C})
__device__ float g_ys[(size_t)Bn*Kn*Ln*Dn];          // (bk,l,d)
__device__ float g_hend[(size_t)Bn*Kn*NC*Dn*Nn];     // (bk,c,d,n)
__device__ float g_S[(size_t)Bn*Kn*NC*Dn];           // (bk,c,d)

__device__ __forceinline__ float ex2f(float x){
    float r; asm("ex2.approx.ftz.f32 %0, %1;" : "=f"(r) : "f"(x)); return r;
}
__device__ __forceinline__ float lg2f(float x){
    float r; asm("lg2.approx.ftz.f32 %0, %1;" : "=f"(r) : "f"(x)); return r;
}

// ---------------------------------------------------------------------------
// Kernel A: cross-scan gather + x_proj + dt_proj + softplus.
// ---------------------------------------------------------------------------
__global__ __launch_bounds__(256, 3) void proj_kernel(
    const float* __restrict__ x, const float* __restrict__ xpw,
    const float* __restrict__ dtw, const float* __restrict__ dtb)
{
    __shared__ float xt[Dn*32];        // xt[d][j]
    __shared__ float dts_s[Rn][32];

    const int bid = blockIdx.x;
    const int t   = bid & 127;
    const int k   = (bid >> 7) & 3;
    const int b   = bid >> 9;
    const int tid = threadIdx.x;

    int l0, lstep, p0, pstep;
    if (k == 0)      { l0 = t*32; lstep = 1;  p0 = t*32;        pstep = 1;  }
    else if (k == 2) { l0 = t*32; lstep = 1;  p0 = 4095 - t*32; pstep = -1; }
    else {
        int h = t & 63, w0 = (t >> 6) * 32;
        p0 = h*64 + w0; pstep = 1;
        if (k == 1) { l0 = w0*64 + h;          lstep = 64;  }
        else        { l0 = 4095 - (w0*64 + h); lstep = -64; }
    }

    const float* xb = x + (size_t)b*Dn*Ln;
    for (int idx = tid; idx < Dn*32; idx += 256) {
        int d = idx >> 5, j = idx & 31;
        xt[idx] = xb[(size_t)d*Ln + p0 + j*pstep];
    }
    __syncthreads();

    {
        const int j = tid & 31;
        const int w = tid >> 5;
        const int l = l0 + j*lstep;
        const size_t bkl = (size_t)(b*Kn + k)*Ln + l;

        float acc[5] = {0.f,0.f,0.f,0.f,0.f};
        const float4* wp[5];
        #pragma unroll
        for (int m = 0; m < 5; m++) {
            int c = w + 8*m; if (c > Cn-1) c = Cn-1;
            wp[m] = (const float4*)(xpw + (size_t)(k*Cn + c)*Dn);
        }
        #pragma unroll 2
        for (int i = 0; i < Dn/4; i++) {
            float x0 = xt[(4*i+0)*32 + j];
            float x1 = xt[(4*i+1)*32 + j];
            float x2 = xt[(4*i+2)*32 + j];
            float x3 = xt[(4*i+3)*32 + j];
            #pragma unroll
            for (int m = 0; m < 5; m++) {
                float4 wv = wp[m][i];
                acc[m] = fmaf(wv.x, x0, acc[m]);
                acc[m] = fmaf(wv.y, x1, acc[m]);
                acc[m] = fmaf(wv.z, x2, acc[m]);
                acc[m] = fmaf(wv.w, x3, acc[m]);
            }
        }
        #pragma unroll
        for (int m = 0; m < 5; m++) {
            int c = w + 8*m;
            if (c < Rn) dts_s[c][j] = acc[m];
            else if (c < Cn) {
                int n = c - Rn, half = 0;
                if (n >= Nn) { n -= Nn; half = 1; }
                g_BC[(bkl*Nn + n)*2 + half] = acc[m];
            }
        }
    }
    __syncthreads();

    for (int idx = tid; idx < Dn*32; idx += 256) {
        int d = idx % Dn, j = idx / Dn;
        float acc = dtb[k*Dn + d];
        #pragma unroll
        for (int r = 0; r < Rn; r++) acc = fmaf(dts_s[r][j], dtw[(k*Dn + d)*Rn + r], acc);
        float e = ex2f(acc * 1.4426950408889634f);
        float sp = 0.6931471805599453f * lg2f(1.f + e);
        if (acc > 20.f) sp = acc;
        float u = xt[d*32 + j];
        int l = l0 + j*lstep;
        size_t o = ((size_t)(b*Kn + k)*Ln + l)*Dn + d;
        ((float2*)g_DU)[o] = make_float2(sp, u);
    }
}

// ---------------------------------------------------------------------------
// Scan pass 1: per-chunk local scan from h=0. Lane owns channel d; A in smem
// (padded, conflict-free); DU prefetched one step ahead.
// ---------------------------------------------------------------------------
__global__ __launch_bounds__(192, 5) void scan_p1(const float* __restrict__ A_logs)
{
    __shared__ float4 sBC[Lc*8];
    __shared__ float sA[Dn*17];
    const int bk = blockIdx.x >> 5;
    const int c  = blockIdx.x & 31;
    const int d  = threadIdx.x;
    const int k  = bk & 3;

    const float4* gbc = (const float4*)(g_BC + ((size_t)bk*Ln + (size_t)c*Lc)*32);
    for (int i = d; i < Lc*8; i += 192) sBC[i] = gbc[i];
    {
        const float4* al = (const float4*)(A_logs + (size_t)(k*Dn + d)*16);
        #pragma unroll
        for (int m = 0; m < 4; m++) {
            float4 v = al[m];
            sA[d*17 + 4*m+0] = -expf(v.x) * 1.4426950408889634f;
            sA[d*17 + 4*m+1] = -expf(v.y) * 1.4426950408889634f;
            sA[d*17 + 4*m+2] = -expf(v.z) * 1.4426950408889634f;
            sA[d*17 + 4*m+3] = -expf(v.w) * 1.4426950408889634f;
        }
    }
    __syncthreads();

    float h[16];
    #pragma unroll
    for (int n = 0; n < 16; n++) h[n] = 0.f;
    float S = 0.f;
    const float2* du = ((const float2*)g_DU) + ((size_t)bk*Ln + (size_t)c*Lc)*Dn + d;
    const float* Ad = sA + d*17;

    float2 nxt = du[0];
    for (int t = 0; t < Lc; t++) {
        float2 cur = nxt;
        if (t+1 < Lc) nxt = du[(size_t)(t+1)*Dn];
        float dt = cur.x, dtu = dt*cur.y;
        S += dt;
        #pragma unroll
        for (int m = 0; m < 8; m++) {
            float4 q = sBC[t*8 + m];
            h[2*m]   = fmaf(ex2f(dt*Ad[2*m]),   h[2*m],   dtu*q.x);
            h[2*m+1] = fmaf(ex2f(dt*Ad[2*m+1]), h[2*m+1], dtu*q.z);
        }
    }
    float4* out = (float4*)(g_hend + (((size_t)bk*NC + c)*Dn + d)*16);
    #pragma unroll
    for (int m = 0; m < 4; m++) out[m] = make_float4(h[4*m], h[4*m+1], h[4*m+2], h[4*m+3]);
    g_S[((size_t)bk*NC + c)*Dn + d] = S;
}

// ---------------------------------------------------------------------------
// Scan mid: chain chunk summaries -> exclusive h_init prefix (in place).
// ---------------------------------------------------------------------------
__global__ __launch_bounds__(256) void scan_mid(const float* __restrict__ A_logs)
{
    int gid = blockIdx.x*256 + threadIdx.x;
    if (gid >= 32*Dn*Nn) return;
    int n  = gid & 15;
    int d  = (gid >> 4) % Dn;
    int bk = gid / (Dn*16);
    int k  = bk & 3;
    float A = -expf(A_logs[(size_t)(k*Dn + d)*16 + n]) * 1.4426950408889634f;
    float h = 0.f;
    for (int c = 0; c < NC; c++) {
        size_t o = (((size_t)bk*NC + c)*Dn + d)*16 + n;
        float hend = g_hend[o];
        float S = g_S[((size_t)bk*NC + c)*Dn + d];
        g_hend[o] = h;
        h = fmaf(ex2f(A*S), h, hend);
    }
}

// ---------------------------------------------------------------------------
// Scan pass 2: rescan chunk from h_init, emit y in (bk,l,d) layout.
// ---------------------------------------------------------------------------
__global__ __launch_bounds__(192, 5) void scan_p2(
    const float* __restrict__ A_logs, const float* __restrict__ Ds)
{
    __shared__ float4 sBC[Lc*8];
    __shared__ float sA[Dn*17];
    const int bk = blockIdx.x >> 5;
    const int c  = blockIdx.x & 31;
    const int d  = threadIdx.x;
    const int k  = bk & 3;

    const float4* gbc = (const float4*)(g_BC + ((size_t)bk*Ln + (size_t)c*Lc)*32);
    for (int i = d; i < Lc*8; i += 192) sBC[i] = gbc[i];
    {
        const float4* al = (const float4*)(A_logs + (size_t)(k*Dn + d)*16);
        #pragma unroll
        for (int m = 0; m < 4; m++) {
            float4 v = al[m];
            sA[d*17 + 4*m+0] = -expf(v.x) * 1.4426950408889634f;
            sA[d*17 + 4*m+1] = -expf(v.y) * 1.4426950408889634f;
            sA[d*17 + 4*m+2] = -expf(v.z) * 1.4426950408889634f;
            sA[d*17 + 4*m+3] = -expf(v.w) * 1.4426950408889634f;
        }
    }
    __syncthreads();

    float h[16];
    const float4* hin = (const float4*)(g_hend + (((size_t)bk*NC + c)*Dn + d)*16);
    #pragma unroll
    for (int m = 0; m < 4; m++) {
        float4 v = hin[m];
        h[4*m+0] = v.x; h[4*m+1] = v.y; h[4*m+2] = v.z; h[4*m+3] = v.w;
    }
    const float Dd = Ds[k*Dn + d];

    const float2* du = ((const float2*)g_DU) + ((size_t)bk*Ln + (size_t)c*Lc)*Dn + d;
    float* yo = g_ys + ((size_t)bk*Ln + (size_t)c*Lc)*Dn + d;
    const float* Ad = sA + d*17;

    float2 nxt = du[0];
    for (int t = 0; t < Lc; t++) {
        float2 cur = nxt;
        if (t+1 < Lc) nxt = du[(size_t)(t+1)*Dn];
        float dt = cur.x, u = cur.y, dtu = dt*u;
        float pa = 0.f, pb = 0.f;
        #pragma unroll
        for (int m = 0; m < 8; m++) {
            float4 q = sBC[t*8 + m];
            h[2*m]   = fmaf(ex2f(dt*Ad[2*m]),   h[2*m],   dtu*q.x);
            h[2*m+1] = fmaf(ex2f(dt*Ad[2*m+1]), h[2*m+1], dtu*q.z);
            pa = fmaf(h[2*m],   q.y, pa);
            pb = fmaf(h[2*m+1], q.w, pb);
        }
        yo[(size_t)t*Dn] = fmaf(Dd, u, pa + pb);
    }
}

// ---------------------------------------------------------------------------
// CrossMerge + LayerNorm.
// ---------------------------------------------------------------------------
__global__ __launch_bounds__(256) void merge_ln_kernel(
    const float* __restrict__ gamma, const float* __restrict__ beta,
    float* __restrict__ out)
{
    const int bid  = blockIdx.x;
    const int b    = bid >> 9;
    const int l    = ((bid & 511) << 3) + (threadIdx.x >> 5);
    const int lane = threadIdx.x & 31;
    const int hh = l >> 6, ww = l & 63;
    const int lT = ww*64 + hh;

    const float* y0 = g_ys + ((size_t)(b*4+0)*Ln + l)*Dn;
    const float* y1 = g_ys + ((size_t)(b*4+1)*Ln + lT)*Dn;
    const float* y2 = g_ys + ((size_t)(b*4+2)*Ln + (4095 - l))*Dn;
    const float* y3 = g_ys + ((size_t)(b*4+3)*Ln + (4095 - lT))*Dn;

    float v[6]; float s = 0.f;
    #pragma unroll
    for (int i = 0; i < 6; i++) {
        int dd = lane + 32*i;
        v[i] = y0[dd] + y1[dd] + y2[dd] + y3[dd];
        s += v[i];
    }
    #pragma unroll
    for (int o = 16; o; o >>= 1) s += __shfl_xor_sync(0xffffffffu, s, o);
    float mean = s * (1.f/192.f);
    float var = 0.f;
    #pragma unroll
    for (int i = 0; i < 6; i++) { float z = v[i] - mean; var = fmaf(z, z, var); }
    #pragma unroll
    for (int o = 16; o; o >>= 1) var += __shfl_xor_sync(0xffffffffu, var, o);
    float rstd = rsqrtf(var*(1.f/192.f) + 1e-5f);

    size_t ob = ((size_t)b*Ln + l)*Dn;
    #pragma unroll
    for (int i = 0; i < 6; i++) {
        int dd = lane + 32*i;
        out[ob + dd] = fmaf((v[i] - mean)*rstd, gamma[dd], beta[dd]);
    }
}

extern "C" void kernel_launch(void* const* d_in, const int* in_sizes, int n_in,
                              void* d_out, int out_size) {
    const float* x    = (const float*)d_in[0];
    const float* xpw  = (const float*)d_in[1];
    const float* dtw  = (const float*)d_in[2];
    const float* dtb  = (const float*)d_in[3];
    const float* Alog = (const float*)d_in[4];
    const float* Ds   = (const float*)d_in[5];
    const float* gam  = (const float*)d_in[6];
    const float* bet  = (const float*)d_in[7];
    float* out = (float*)d_out;

    proj_kernel<<<Bn*Kn*128, 256>>>(x, xpw, dtw, dtb);
    scan_p1<<<32*NC, 192>>>(Alog);
    scan_mid<<<(32*Dn*Nn + 255)/256, 256>>>(Alog);
    scan_p2<<<32*NC, 192>>>(Alog, Ds);
    merge_ln_kernel<<<Bn*512, 256>>>(gam, bet, out);
}